// round 1
// baseline (speedup 1.0000x reference)
#include <cuda_runtime.h>
#include <cstdint>
#include <cstddef>

// Problem constants (fixed by the dataset): B=16, T=2048, D=1024, E=4D=4096
#define BB 16
#define TT 2048
#define DD 1024
#define EE 4096

#define REC_BLOCKS 128          // persistent blocks, 1 per SM (<=148)
#define DPB (DD / REC_BLOCKS)   // 8 d-columns per block

// ---------------------------------------------------------------------------
// Device scratch (no cudaMalloc allowed): xg = x @ Wi  (512 MB), h ping-pong,
// and grid-barrier state.
// ---------------------------------------------------------------------------
__device__ float    g_xg[(size_t)BB * TT * EE];
__device__ float    g_h[2][DD * BB];        // [buf][d*16 + b]  (k-major, 16 batches)
__device__ unsigned g_bar_count = 0;
__device__ unsigned g_bar_gen   = 0;

// ---------------------------------------------------------------------------
// Software grid barrier (sense/generation based). All REC_BLOCKS blocks are
// co-resident (1 block/SM, grid=128 <= 148 SMs), so spinning is safe.
// ---------------------------------------------------------------------------
__device__ __forceinline__ void grid_barrier(unsigned nblocks) {
    __threadfence();            // make this thread's global writes visible
    __syncthreads();
    if (threadIdx.x == 0) {
        unsigned gen = atomicAdd(&g_bar_gen, 0u);
        unsigned arr = atomicAdd(&g_bar_count, 1u);
        if (arr == nblocks - 1u) {
            atomicExch(&g_bar_count, 0u);
            __threadfence();
            atomicAdd(&g_bar_gen, 1u);          // release
        } else {
            while (atomicAdd(&g_bar_gen, 0u) == gen) { __nanosleep(64); }
        }
    }
    __syncthreads();
}

// ---------------------------------------------------------------------------
// Phase 1: xg = x @ Wi   (M=32768, K=1024, N=4096), fp32 SGEMM.
// 128x128 block tile, BK=8, 256 threads, 8x8 register tile, register prefetch.
// ---------------------------------------------------------------------------
__global__ __launch_bounds__(256) void gemm_xg_kernel(
    const float* __restrict__ A,   // x   (32768 x 1024) row-major
    const float* __restrict__ W)   // Wi  (1024 x 4096)  row-major
{
    __shared__ float As[8][128];   // [k][m]  (transposed on store)
    __shared__ float Bs[8][128];   // [k][n]

    const int tid = threadIdx.x;
    const int m0 = blockIdx.y * 128;
    const int n0 = blockIdx.x * 128;

    // compute-thread mapping: warp covers 4(ty) x 8(tx) micro-tiles
    const int w  = tid >> 5, l = tid & 31;
    const int ty = ((w >> 1) << 2) + (l >> 3);   // 0..15
    const int tx = ((w & 1) << 3) + (l & 7);     // 0..15

    // global-load mapping
    const int am = tid >> 1;            // 0..127 (row of A tile)
    const int ak = (tid & 1) << 2;      // 0 or 4
    const int bk = tid >> 5;            // 0..7   (row of B tile)
    const int bn = (tid & 31) << 2;     // 0..124

    const float* aG = A + (size_t)(m0 + am) * DD + ak;
    const float* bG = W + (size_t)bk * EE + n0 + bn;

    float4 aR = *(const float4*)aG;
    float4 bR = *(const float4*)bG;

    float acc[8][8];
#pragma unroll
    for (int i = 0; i < 8; ++i)
#pragma unroll
        for (int j = 0; j < 8; ++j) acc[i][j] = 0.f;

    for (int k0 = 0; k0 < DD; k0 += 8) {
        As[ak + 0][am] = aR.x;
        As[ak + 1][am] = aR.y;
        As[ak + 2][am] = aR.z;
        As[ak + 3][am] = aR.w;
        *(float4*)&Bs[bk][bn] = bR;
        __syncthreads();

        if (k0 + 8 < DD) {
            aR = *(const float4*)(aG + (k0 + 8));
            bR = *(const float4*)(bG + (size_t)(k0 + 8) * EE);
        }

#pragma unroll
        for (int kk = 0; kk < 8; ++kk) {
            float4 a0 = *(const float4*)&As[kk][ty << 3];
            float4 a1 = *(const float4*)&As[kk][(ty << 3) + 4];
            float4 b0 = *(const float4*)&Bs[kk][tx << 3];
            float4 b1 = *(const float4*)&Bs[kk][(tx << 3) + 4];
            float av[8] = {a0.x, a0.y, a0.z, a0.w, a1.x, a1.y, a1.z, a1.w};
            float bv[8] = {b0.x, b0.y, b0.z, b0.w, b1.x, b1.y, b1.z, b1.w};
#pragma unroll
            for (int i = 0; i < 8; ++i)
#pragma unroll
                for (int j = 0; j < 8; ++j) acc[i][j] += av[i] * bv[j];
        }
        __syncthreads();
    }

#pragma unroll
    for (int i = 0; i < 8; ++i) {
        float* cRow = g_xg + (size_t)(m0 + (ty << 3) + i) * EE + n0 + (tx << 3);
        float4 v0 = make_float4(acc[i][0], acc[i][1], acc[i][2], acc[i][3]);
        float4 v1 = make_float4(acc[i][4], acc[i][5], acc[i][6], acc[i][7]);
        *(float4*)cRow       = v0;
        *(float4*)(cRow + 4) = v1;
    }
}

// ---------------------------------------------------------------------------
// Phase 2: persistent recurrence kernel.
// 128 blocks x 256 threads. Block bx owns d-columns [8*bx, 8*bx+8) and their
// 4 gate columns in Wh; the 1024x32 Wh slice lives in smem for all 2048 steps.
//
// smem: w_sh[1024][36]  (k-major, 32 cols + pad4)       = 147456 B
//       h_sh[1024][16]  (k-major, 16 batches)           =  65536 B
//       red  aliases h_sh after the dot phase (8*16*36) =  18432 B (reuse)
// total dynamic smem = 212992 B  (1 block/SM)
//
// Thread work per step: (bg in 0..3: 4 batches) x (cg in 0..3: 8 cols) x
// (ks in 0..15: 64 of 1024 k, interleaved in float4 chunks) -> 2048 FMA.
// ---------------------------------------------------------------------------
#define REC_SMEM_FLOATS (1024 * 36 + 1024 * 16)
#define REC_SMEM_BYTES  (REC_SMEM_FLOATS * 4)

__global__ __launch_bounds__(256, 1) void lstm_rec_kernel(
    const float* __restrict__ carry,   // (16, 1024, 2): [...,0]=h0, [...,1]=c0
    const float* __restrict__ Wh,      // (1024, 4096) row-major
    const float* __restrict__ bias,    // (4096,)
    float* __restrict__ dout)          // out (16,2048,1024) then carry (16,1024,2)
{
    extern __shared__ float sm[];
    float* w_sh = sm;                  // [k][36], cols c = gate*8 + dl
    float* h_sh = sm + 1024 * 36;      // [k][16]
    float* red  = h_sh;                // aliased after dot phase: [8][16][36]

    const int tid = threadIdx.x;
    const int d0  = blockIdx.x * DPB;

    // ---- load Wh slice into smem (one time) ----
    for (int idx = tid; idx < 1024 * 32; idx += 256) {
        int k = idx >> 5, c = idx & 31;
        int e = ((c >> 3) << 10) + d0 + (c & 7);   // gate*1024 + dglobal
        w_sh[k * 36 + c] = Wh[(size_t)k * EE + e];
    }

    // ---- init h0 into g_h[0], c into registers, preload bias ----
    float c_reg = 0.f, h_last = 0.f, bi = 0.f, bf = 0.f, bgt = 0.f, bo = 0.f;
    int pb = 0, pd = 0, pdg = 0;
    if (tid < 128) {
        pb  = tid & 15;          // batch
        pd  = tid >> 4;          // local d (0..7)
        pdg = d0 + pd;           // global d
        g_h[0][pdg * 16 + pb] = carry[((size_t)pb * DD + pdg) * 2 + 0];
        c_reg                 = carry[((size_t)pb * DD + pdg) * 2 + 1];
        bi  = bias[pdg];
        bf  = bias[DD + pdg];
        bgt = bias[2 * DD + pdg];
        bo  = bias[3 * DD + pdg];
    }
    grid_barrier(gridDim.x);    // also covers w_sh visibility within block

    const int  bg      = tid & 3;            // batch group (4 batches)
    const int  cg      = (tid >> 2) & 3;     // column group (8 cols)
    const int  ks      = tid >> 4;           // k-split 0..15
    const int  kp      = ks >> 1;
    const bool ks_even = (ks & 1) == 0;

    float* nc = dout + (size_t)BB * TT * DD; // new_carry region

    for (int t = 0; t < TT; ++t) {
        // ---- stage h_t (16 KB-floats = 64 KB) from L2, bypass L1 ----
        const float4* hin = (const float4*)g_h[t & 1];
#pragma unroll
        for (int r = 0; r < 16; ++r) {
            ((float4*)h_sh)[r * 256 + tid] = __ldcg(hin + r * 256 + tid);
        }

        // ---- prefetch xg[t] for the gate threads (hidden under the dots) ----
        float xgi = 0.f, xgf = 0.f, xgg = 0.f, xgo = 0.f;
        if (tid < 128) {
            const float* xr = g_xg + ((size_t)(pb * TT + t)) * EE + pdg;
            xgi = __ldg(xr);
            xgf = __ldg(xr + DD);
            xgg = __ldg(xr + 2 * DD);
            xgo = __ldg(xr + 3 * DD);
        }
        __syncthreads();

        // ---- partial dot products: h[4b] x Wh[8c] over 64 k ----
        float4 acc0[4], acc1[4];
#pragma unroll
        for (int i = 0; i < 4; ++i) {
            acc0[i] = make_float4(0.f, 0.f, 0.f, 0.f);
            acc1[i] = make_float4(0.f, 0.f, 0.f, 0.f);
        }

#pragma unroll 4
        for (int m = 0; m < 16; ++m) {
            int kb = (ks + (m << 4)) << 2;           // starting k of this chunk
            const float* hp = h_sh + kb * 16 + (bg << 2);
            const float* wp = w_sh + kb * 36 + (cg << 3);
#pragma unroll
            for (int kk = 0; kk < 4; ++kk) {
                float4 hb = *(const float4*)hp;      // 4 batches at this k
                float4 w0 = *(const float4*)wp;      // cols c..c+3
                float4 w1 = *(const float4*)(wp + 4);// cols c+4..c+7
                hp += 16;
                wp += 36;
                float hv[4] = {hb.x, hb.y, hb.z, hb.w};
#pragma unroll
                for (int i = 0; i < 4; ++i) {
                    acc0[i].x += hv[i] * w0.x;  acc0[i].y += hv[i] * w0.y;
                    acc0[i].z += hv[i] * w0.z;  acc0[i].w += hv[i] * w0.w;
                    acc1[i].x += hv[i] * w1.x;  acc1[i].y += hv[i] * w1.y;
                    acc1[i].z += hv[i] * w1.z;  acc1[i].w += hv[i] * w1.w;
                }
            }
        }

        // ---- reduce adjacent ks pairs in-warp (lane ^ 16 differs only in ks) ----
#pragma unroll
        for (int i = 0; i < 4; ++i) {
            acc0[i].x += __shfl_xor_sync(0xffffffffu, acc0[i].x, 16);
            acc0[i].y += __shfl_xor_sync(0xffffffffu, acc0[i].y, 16);
            acc0[i].z += __shfl_xor_sync(0xffffffffu, acc0[i].z, 16);
            acc0[i].w += __shfl_xor_sync(0xffffffffu, acc0[i].w, 16);
            acc1[i].x += __shfl_xor_sync(0xffffffffu, acc1[i].x, 16);
            acc1[i].y += __shfl_xor_sync(0xffffffffu, acc1[i].y, 16);
            acc1[i].z += __shfl_xor_sync(0xffffffffu, acc1[i].z, 16);
            acc1[i].w += __shfl_xor_sync(0xffffffffu, acc1[i].w, 16);
        }

        __syncthreads();   // everyone done READING h_sh before it becomes red

        if (ks_even) {
#pragma unroll
            for (int i = 0; i < 4; ++i) {
                float* rp = red + ((kp * 16 + (bg << 2) + i) * 36) + (cg << 3);
                *(float4*)rp       = acc0[i];
                *(float4*)(rp + 4) = acc1[i];
            }
        }
        __syncthreads();

        // ---- final reduce + gates + state update (128 "pair" threads) ----
        if (tid < 128) {
            float gi = xgi + bi, gf = xgf + bf, gg = xgg + bgt, go = xgo + bo;
#pragma unroll
            for (int q = 0; q < 8; ++q) {
                const float* rp = red + (q * 16 + pb) * 36;
                gi += rp[pd];
                gf += rp[8 + pd];
                gg += rp[16 + pd];
                go += rp[24 + pd];
            }
            float iv = 1.f / (1.f + expf(-gi));
            float fv = 1.f / (1.f + expf(-gf));
            float gv = tanhf(gg);
            float ov = 1.f / (1.f + expf(-go));
            c_reg    = fv * c_reg + iv * gv;
            float hv = ov * tanhf(c_reg);
            h_last   = hv;
            g_h[(t + 1) & 1][pdg * 16 + pb]       = hv;  // publish h_{t+1}
            dout[((size_t)pb * TT + t) * DD + pdg] = hv; // out[b,t,d]
        }
        grid_barrier(gridDim.x);
    }

    // ---- final carry: (B, D, 2) = stack([hT, cT], -1) ----
    if (tid < 128) {
        nc[((size_t)pb * DD + pdg) * 2 + 0] = h_last;
        nc[((size_t)pb * DD + pdg) * 2 + 1] = c_reg;
    }
}

// ---------------------------------------------------------------------------
// Launch
// ---------------------------------------------------------------------------
extern "C" void kernel_launch(void* const* d_in, const int* in_sizes, int n_in,
                              void* d_out, int out_size) {
    (void)in_sizes; (void)n_in; (void)out_size;
    const float* x     = (const float*)d_in[0];  // (16, 2048, 1024)
    const float* carry = (const float*)d_in[1];  // (16, 1024, 2)
    const float* Wi    = (const float*)d_in[2];  // (1024, 4096)
    const float* Wh    = (const float*)d_in[3];  // (1024, 4096)
    const float* b     = (const float*)d_in[4];  // (4096,)
    float* out = (float*)d_out;

    // Phase 1: xg = x @ Wi  -> g_xg
    dim3 ggrid(EE / 128, (BB * TT) / 128);
    gemm_xg_kernel<<<ggrid, 256>>>(x, Wi);

    // Phase 2: persistent recurrence
    cudaFuncSetAttribute(lstm_rec_kernel,
                         cudaFuncAttributeMaxDynamicSharedMemorySize,
                         REC_SMEM_BYTES);
    lstm_rec_kernel<<<REC_BLOCKS, 256, REC_SMEM_BYTES>>>(carry, Wh, b, out);
}

// round 2
// speedup vs baseline: 1.2879x; 1.2879x over previous
#include <cuda_runtime.h>
#include <cuda_bf16.h>
#include <cstdint>
#include <cstddef>

// Problem constants: B=16, T=2048, D=1024, E=4D=4096
#define BB 16
#define TT 2048
#define DD 1024
#define EE 4096

#define REC_BLOCKS 128          // persistent blocks, 1 per SM
#define DPB (DD / REC_BLOCKS)   // 8 d-columns per block

// ---------------------------------------------------------------------------
// Device scratch (no cudaMalloc allowed)
// ---------------------------------------------------------------------------
__device__ float g_xg[(size_t)BB * TT * EE];                 // x @ Wi

// h published in mma A-fragment order, bf16 hi/lo split.
// Layout per buffer: [64 kslices][32 lanes][8 words]; words 0..3 = hi a0..a3,
// words 4..7 = lo a0..a7.  65536 B per buffer.
__device__ __align__(16) uint32_t g_hfrag[2][64 * 32 * 8];

// Two-level grid barrier state (monotonic counters; survive graph replays)
__device__ unsigned g_cnt2[16 * 64];   // 16 group counters, 256B apart
__device__ unsigned g_master2[64];
__device__ unsigned g_gen2;

// ---------------------------------------------------------------------------
// Two-level grid barrier.  s = 0,1,2,... per call; base = g_gen2 at entry.
// 16 groups of 8 blocks -> at most 8 serialized atomics per address.
// ---------------------------------------------------------------------------
__device__ __forceinline__ void grid_barrier2(unsigned s, unsigned base) {
    __syncthreads();
    if (threadIdx.x == 0) {
        __threadfence();
        unsigned g = blockIdx.x & 15u;
        if (atomicAdd(&g_cnt2[g * 64], 1u) == (base + s) * 8u + 7u) {
            if (atomicAdd(&g_master2[0], 1u) == (base + s) * 16u + 15u) {
                unsigned nv = base + s + 1u;
                asm volatile("st.global.release.gpu.u32 [%0], %1;"
                             :: "l"(&g_gen2), "r"(nv) : "memory");
            }
        }
        unsigned cur;
        do {
            asm volatile("ld.global.acquire.gpu.u32 %0, [%1];"
                         : "=r"(cur) : "l"(&g_gen2) : "memory");
            if (cur > base + s) break;
            __nanosleep(32);
        } while (true);
    }
    __syncthreads();
}

// ---------------------------------------------------------------------------
// bf16 mma m16n8k16, fp32 accumulate
// ---------------------------------------------------------------------------
__device__ __forceinline__ void mma_bf16(float4& c, const uint4& a,
                                         uint32_t b0, uint32_t b1) {
    asm volatile(
        "mma.sync.aligned.m16n8k16.row.col.f32.bf16.bf16.f32 "
        "{%0,%1,%2,%3}, {%4,%5,%6,%7}, {%8,%9}, {%0,%1,%2,%3};\n"
        : "+f"(c.x), "+f"(c.y), "+f"(c.z), "+f"(c.w)
        : "r"(a.x), "r"(a.y), "r"(a.z), "r"(a.w), "r"(b0), "r"(b1));
}

__device__ __forceinline__ void split_bf16(float v, __nv_bfloat16& hi,
                                           __nv_bfloat16& lo) {
    hi = __float2bfloat16(v);
    lo = __float2bfloat16(v - __bfloat162float(hi));
}

// ---------------------------------------------------------------------------
// Phase 1: xg = x @ Wi   (M=32768, K=1024, N=4096), fp32 SGEMM (unchanged)
// ---------------------------------------------------------------------------
__global__ __launch_bounds__(256) void gemm_xg_kernel(
    const float* __restrict__ A,
    const float* __restrict__ W)
{
    __shared__ float As[8][128];
    __shared__ float Bs[8][128];

    const int tid = threadIdx.x;
    const int m0 = blockIdx.y * 128;
    const int n0 = blockIdx.x * 128;

    const int w  = tid >> 5, l = tid & 31;
    const int ty = ((w >> 1) << 2) + (l >> 3);
    const int tx = ((w & 1) << 3) + (l & 7);

    const int am = tid >> 1;
    const int ak = (tid & 1) << 2;
    const int bk = tid >> 5;
    const int bn = (tid & 31) << 2;

    const float* aG = A + (size_t)(m0 + am) * DD + ak;
    const float* bG = W + (size_t)bk * EE + n0 + bn;

    float4 aR = *(const float4*)aG;
    float4 bR = *(const float4*)bG;

    float acc[8][8];
#pragma unroll
    for (int i = 0; i < 8; ++i)
#pragma unroll
        for (int j = 0; j < 8; ++j) acc[i][j] = 0.f;

    for (int k0 = 0; k0 < DD; k0 += 8) {
        As[ak + 0][am] = aR.x;
        As[ak + 1][am] = aR.y;
        As[ak + 2][am] = aR.z;
        As[ak + 3][am] = aR.w;
        *(float4*)&Bs[bk][bn] = bR;
        __syncthreads();

        if (k0 + 8 < DD) {
            aR = *(const float4*)(aG + (k0 + 8));
            bR = *(const float4*)(bG + (size_t)(k0 + 8) * EE);
        }

#pragma unroll
        for (int kk = 0; kk < 8; ++kk) {
            float4 a0 = *(const float4*)&As[kk][ty << 3];
            float4 a1 = *(const float4*)&As[kk][(ty << 3) + 4];
            float4 b0 = *(const float4*)&Bs[kk][tx << 3];
            float4 b1 = *(const float4*)&Bs[kk][(tx << 3) + 4];
            float av[8] = {a0.x, a0.y, a0.z, a0.w, a1.x, a1.y, a1.z, a1.w};
            float bv[8] = {b0.x, b0.y, b0.z, b0.w, b1.x, b1.y, b1.z, b1.w};
#pragma unroll
            for (int i = 0; i < 8; ++i)
#pragma unroll
                for (int j = 0; j < 8; ++j) acc[i][j] += av[i] * bv[j];
        }
        __syncthreads();
    }

#pragma unroll
    for (int i = 0; i < 8; ++i) {
        float* cRow = g_xg + (size_t)(m0 + (ty << 3) + i) * EE + n0 + (tx << 3);
        float4 v0 = make_float4(acc[i][0], acc[i][1], acc[i][2], acc[i][3]);
        float4 v1 = make_float4(acc[i][4], acc[i][5], acc[i][6], acc[i][7]);
        *(float4*)cRow       = v0;
        *(float4*)(cRow + 4) = v1;
    }
}

// ---------------------------------------------------------------------------
// Phase 2: persistent recurrence via bf16x2-split tensor-core MMA.
//
// Block bx owns 32 output columns: gate n (0..3) x dl (0..7), e = n*1024+d0+dl.
// smem: Wh fragments hi/lo = 4 ntiles x 64 kslices x 32 lanes x 16B = 128 KB
//       reduction area      = 8 warps x 4 ntiles x 32 lanes x 16B  =  16 KB
// Each of 8 warps handles one k-split (128 k = 8 kslices) x all 4 ntiles:
// per step 8 x 4 x 3 = 96 MMAs -> partial C, reduced via smem.
// ---------------------------------------------------------------------------
#define W_WORDS (4 * 64 * 32 * 4)              // 32768 words = 128 KB
#define REC_SMEM_BYTES (W_WORDS * 4 + 8 * 4 * 32 * 4 * 4)  // 147456 B

__global__ __launch_bounds__(256, 1) void lstm_rec_kernel(
    const float* __restrict__ carry,   // (16, 1024, 2)
    const float* __restrict__ Wh,      // (1024, 4096)
    const float* __restrict__ bias,    // (4096,)
    float* __restrict__ dout)          // out (16,2048,1024) then carry
{
    extern __shared__ uint32_t sm_w[];              // Wh fragments
    float* red = (float*)(sm_w + W_WORDS);          // [w][n][lane][4]

    const int tid  = threadIdx.x;
    const int w    = tid >> 5;
    const int lane = tid & 31;
    const int d0   = blockIdx.x * DPB;

    unsigned bar_base = 0;
    if (tid == 0) {
        asm volatile("ld.global.acquire.gpu.u32 %0, [%1];"
                     : "=r"(bar_base) : "l"(&g_gen2) : "memory");
    }
    bar_base = __shfl_sync(0xffffffffu, bar_base, 0);
    __shared__ unsigned sh_base;
    if (tid == 0) sh_base = bar_base;

    // ---- pack Wh slice into smem as mma B fragments (hi/lo bf16) ----
    for (int idx = tid; idx < 4 * 64 * 32 * 2; idx += 256) {
        int n    = idx >> 12;          // / 4096
        int rem  = idx & 4095;
        int ks   = rem >> 6;
        int rem2 = rem & 63;
        int ln   = rem2 >> 1;
        int reg  = rem2 & 1;
        int tig  = ln & 3;
        int dl   = ln >> 2;
        int kb   = ks * 16 + reg * 8 + tig * 2;
        size_t col = (size_t)n * DD + d0 + dl;
        float v0 = Wh[(size_t)kb * EE + col];
        float v1 = Wh[(size_t)(kb + 1) * EE + col];
        __nv_bfloat16 h0, l0, h1, l1;
        split_bf16(v0, h0, l0);
        split_bf16(v1, h1, l1);
        uint32_t whi = (uint32_t)__bfloat16_as_ushort(h0) |
                       ((uint32_t)__bfloat16_as_ushort(h1) << 16);
        uint32_t wlo = (uint32_t)__bfloat16_as_ushort(l0) |
                       ((uint32_t)__bfloat16_as_ushort(l1) << 16);
        uint32_t* wp = sm_w + (size_t)(((n * 64 + ks) * 32 + ln)) * 4;
        wp[reg]     = whi;
        wp[2 + reg] = wlo;
    }

    // ---- per-gate-thread constants (tid < 128): pd = d local, pb = batch ----
    float c_reg = 0.f, h_last = 0.f, bi = 0.f, bf_ = 0.f, bgt = 0.f, bo = 0.f;
    int pb = 0, pd = 0, pdg = 0, hoff = 0, lane_c = 0, reg_c = 0;
    if (tid < 128) {
        pd  = tid & 7;
        pb  = tid >> 3;
        pdg = d0 + pd;
        // A-fragment slot for element (row=pb, col k=pdg)
        int ksp  = pdg >> 4;
        int cc   = pdg & 15;
        int lnp  = (pb & 7) * 4 + ((cc & 7) >> 1);
        int regp = ((pb >> 3) & 1) + 2 * ((cc >> 3) & 1);
        hoff = ((ksp * 32 + lnp) * 8 + regp) * 4 + (cc & 1) * 2;   // byte offset
        // C-fragment slot for element (row=pb, col=pd)
        lane_c = (pb & 7) * 4 + (pd >> 1);
        reg_c  = 2 * (pb >> 3) + (pd & 1);

        c_reg = carry[((size_t)pb * DD + pdg) * 2 + 1];
        float h0v = carry[((size_t)pb * DD + pdg) * 2 + 0];
        bi  = bias[pdg];
        bf_ = bias[DD + pdg];
        bgt = bias[2 * DD + pdg];
        bo  = bias[3 * DD + pdg];

        // publish h0 fragments into buffer 0
        char* hb = (char*)g_hfrag;
        __nv_bfloat16 hhi, hlo;
        split_bf16(h0v, hhi, hlo);
        *(__nv_bfloat16*)(hb + hoff)      = hhi;
        *(__nv_bfloat16*)(hb + hoff + 16) = hlo;
    }
    __syncthreads();
    bar_base = sh_base;

    grid_barrier2(0u, bar_base);

    float* nc = dout + (size_t)BB * TT * DD;

    for (int t = 0; t < TT; ++t) {
        // ---- xg prefetch for gate threads (overlaps with MMAs) ----
        float xgi = 0.f, xgf = 0.f, xgg = 0.f, xgo = 0.f;
        if (tid < 128) {
            const float* xr = g_xg + ((size_t)pb * TT + t) * EE + pdg;
            xgi = __ldg(xr);
            xgf = __ldg(xr + DD);
            xgg = __ldg(xr + 2 * DD);
            xgo = __ldg(xr + 3 * DD);
        }

        // ---- MMA over this warp's k range (8 kslices x 4 ntiles x 3) ----
        float4 acc[4];
#pragma unroll
        for (int n = 0; n < 4; ++n) acc[n] = make_float4(0.f, 0.f, 0.f, 0.f);

        const uint4* ab = (const uint4*)g_hfrag[t & 1];
#pragma unroll
        for (int j = 0; j < 8; ++j) {
            int ks = w * 8 + j;
            uint4 ahi = __ldcg(ab + (ks * 32 + lane) * 2);
            uint4 alo = __ldcg(ab + (ks * 32 + lane) * 2 + 1);
#pragma unroll
            for (int n = 0; n < 4; ++n) {
                uint4 b = *(const uint4*)(sm_w + (size_t)(((n * 64 + ks) * 32 + lane)) * 4);
                mma_bf16(acc[n], ahi, b.x, b.y);   // hi * hi
                mma_bf16(acc[n], ahi, b.z, b.w);   // hi * lo
                mma_bf16(acc[n], alo, b.x, b.y);   // lo * hi
            }
        }

        // ---- write partial C to smem, reduce across the 8 k-split warps ----
#pragma unroll
        for (int n = 0; n < 4; ++n) {
            *(float4*)(red + (size_t)(((w * 4 + n) * 32 + lane)) * 4) = acc[n];
        }
        __syncthreads();

        if (tid < 128) {
            float gi = xgi + bi, gf = xgf + bf_, gg = xgg + bgt, go = xgo + bo;
#pragma unroll
            for (int q = 0; q < 8; ++q) {
                const float* rp = red + (size_t)(q * 4) * 128;
                gi += rp[lane_c * 4 + reg_c];
                gf += rp[128 + lane_c * 4 + reg_c];
                gg += rp[256 + lane_c * 4 + reg_c];
                go += rp[384 + lane_c * 4 + reg_c];
            }
            float iv = 1.f / (1.f + expf(-gi));
            float fv = 1.f / (1.f + expf(-gf));
            float gv = tanhf(gg);
            float ov = 1.f / (1.f + expf(-go));
            c_reg    = fv * c_reg + iv * gv;
            float hv = ov * tanhf(c_reg);
            h_last   = hv;

            // publish h_{t+1} fragments
            char* hb = (char*)g_hfrag + (size_t)((t + 1) & 1) * (64 * 32 * 32);
            __nv_bfloat16 hhi, hlo;
            split_bf16(hv, hhi, hlo);
            *(__nv_bfloat16*)(hb + hoff)      = hhi;
            *(__nv_bfloat16*)(hb + hoff + 16) = hlo;

            dout[((size_t)pb * TT + t) * DD + pdg] = hv;
        }
        grid_barrier2((unsigned)(t + 1), bar_base);
    }

    if (tid < 128) {
        nc[((size_t)pb * DD + pdg) * 2 + 0] = h_last;
        nc[((size_t)pb * DD + pdg) * 2 + 1] = c_reg;
    }
}

// ---------------------------------------------------------------------------
// Launch
// ---------------------------------------------------------------------------
extern "C" void kernel_launch(void* const* d_in, const int* in_sizes, int n_in,
                              void* d_out, int out_size) {
    (void)in_sizes; (void)n_in; (void)out_size;
    const float* x     = (const float*)d_in[0];  // (16, 2048, 1024)
    const float* carry = (const float*)d_in[1];  // (16, 1024, 2)
    const float* Wi    = (const float*)d_in[2];  // (1024, 4096)
    const float* Wh    = (const float*)d_in[3];  // (1024, 4096)
    const float* b     = (const float*)d_in[4];  // (4096,)
    float* out = (float*)d_out;

    dim3 ggrid(EE / 128, (BB * TT) / 128);
    gemm_xg_kernel<<<ggrid, 256>>>(x, Wi);

    cudaFuncSetAttribute(lstm_rec_kernel,
                         cudaFuncAttributeMaxDynamicSharedMemorySize,
                         REC_SMEM_BYTES);
    lstm_rec_kernel<<<REC_BLOCKS, 256, REC_SMEM_BYTES>>>(carry, Wh, b, out);
}

// round 3
// speedup vs baseline: 1.4779x; 1.1475x over previous
#include <cuda_runtime.h>
#include <cuda_bf16.h>
#include <cstdint>
#include <cstddef>

// Problem constants: B=16, T=2048, D=1024, E=4D=4096
#define BB 16
#define TT 2048
#define DD 1024
#define EE 4096

#define REC_BLOCKS 128          // persistent blocks, 1 per SM
#define DPB (DD / REC_BLOCKS)   // 8 d-columns per block

// ---------------------------------------------------------------------------
// Device scratch (no cudaMalloc allowed)
// ---------------------------------------------------------------------------
__device__ float g_xg[(size_t)BB * TT * EE];                 // x @ Wi

// h in mma A-fragment order, hi/lo interleaved per register:
// word index = (ks*32 + lane)*8 + 2*reg + {0:hi, 1:lo}.  64 KB per buffer.
__device__ __align__(16) uint32_t g_hfrag[2][64 * 32 * 8];

// Fine-grained producer flags: one counter per k-group (warp id 0..7),
// spaced 256 B.  Reset to 0 at end of every run by the last block.
__device__ unsigned g_flags[8 * 64];
__device__ unsigned g_endcnt;          // monotonic across graph replays

// ---------------------------------------------------------------------------
// bf16 mma m16n8k16, fp32 accumulate
// ---------------------------------------------------------------------------
__device__ __forceinline__ void mma_bf16(float4& c, const uint4& a,
                                         uint32_t b0, uint32_t b1) {
    asm volatile(
        "mma.sync.aligned.m16n8k16.row.col.f32.bf16.bf16.f32 "
        "{%0,%1,%2,%3}, {%4,%5,%6,%7}, {%8,%9}, {%0,%1,%2,%3};\n"
        : "+f"(c.x), "+f"(c.y), "+f"(c.z), "+f"(c.w)
        : "r"(a.x), "r"(a.y), "r"(a.z), "r"(a.w), "r"(b0), "r"(b1));
}

__device__ __forceinline__ void split_bf16(float v, __nv_bfloat16& hi,
                                           __nv_bfloat16& lo) {
    hi = __float2bfloat16(v);
    lo = __float2bfloat16(v - __bfloat162float(hi));
}

__device__ __forceinline__ float fast_sigmoid(float x) {
    return __fdividef(1.f, 1.f + __expf(-x));
}
__device__ __forceinline__ float fast_tanh(float x) {
    return __fdividef(2.f, 1.f + __expf(-2.f * x)) - 1.f;
}

// ---------------------------------------------------------------------------
// Phase 1: xg = x @ Wi   (M=32768, K=1024, N=4096), fp32 SGEMM (unchanged)
// ---------------------------------------------------------------------------
__global__ __launch_bounds__(256) void gemm_xg_kernel(
    const float* __restrict__ A,
    const float* __restrict__ W)
{
    __shared__ float As[8][128];
    __shared__ float Bs[8][128];

    const int tid = threadIdx.x;
    const int m0 = blockIdx.y * 128;
    const int n0 = blockIdx.x * 128;

    const int w  = tid >> 5, l = tid & 31;
    const int ty = ((w >> 1) << 2) + (l >> 3);
    const int tx = ((w & 1) << 3) + (l & 7);

    const int am = tid >> 1;
    const int ak = (tid & 1) << 2;
    const int bk = tid >> 5;
    const int bn = (tid & 31) << 2;

    const float* aG = A + (size_t)(m0 + am) * DD + ak;
    const float* bG = W + (size_t)bk * EE + n0 + bn;

    float4 aR = *(const float4*)aG;
    float4 bR = *(const float4*)bG;

    float acc[8][8];
#pragma unroll
    for (int i = 0; i < 8; ++i)
#pragma unroll
        for (int j = 0; j < 8; ++j) acc[i][j] = 0.f;

    for (int k0 = 0; k0 < DD; k0 += 8) {
        As[ak + 0][am] = aR.x;
        As[ak + 1][am] = aR.y;
        As[ak + 2][am] = aR.z;
        As[ak + 3][am] = aR.w;
        *(float4*)&Bs[bk][bn] = bR;
        __syncthreads();

        if (k0 + 8 < DD) {
            aR = *(const float4*)(aG + (k0 + 8));
            bR = *(const float4*)(bG + (size_t)(k0 + 8) * EE);
        }

#pragma unroll
        for (int kk = 0; kk < 8; ++kk) {
            float4 a0 = *(const float4*)&As[kk][ty << 3];
            float4 a1 = *(const float4*)&As[kk][(ty << 3) + 4];
            float4 b0 = *(const float4*)&Bs[kk][tx << 3];
            float4 b1 = *(const float4*)&Bs[kk][(tx << 3) + 4];
            float av[8] = {a0.x, a0.y, a0.z, a0.w, a1.x, a1.y, a1.z, a1.w};
            float bv[8] = {b0.x, b0.y, b0.z, b0.w, b1.x, b1.y, b1.z, b1.w};
#pragma unroll
            for (int i = 0; i < 8; ++i)
#pragma unroll
                for (int j = 0; j < 8; ++j) acc[i][j] += av[i] * bv[j];
        }
        __syncthreads();
    }

#pragma unroll
    for (int i = 0; i < 8; ++i) {
        float* cRow = g_xg + (size_t)(m0 + (ty << 3) + i) * EE + n0 + (tx << 3);
        float4 v0 = make_float4(acc[i][0], acc[i][1], acc[i][2], acc[i][3]);
        float4 v1 = make_float4(acc[i][4], acc[i][5], acc[i][6], acc[i][7]);
        *(float4*)cRow       = v0;
        *(float4*)(cRow + 4) = v1;
    }
}

// ---------------------------------------------------------------------------
// Phase 2: persistent recurrence, bf16x2-split MMA + fine-grained flags.
// Warp w consumes kslices [8w, 8w+8) == h values produced by blocks
// [16w, 16w+16).  It polls only g_flags[w] — no global barrier in the loop.
// smem: Wh fragments 128 KB + double-buffered reduction 2 x 16 KB.
// ---------------------------------------------------------------------------
#define W_WORDS (4 * 64 * 32 * 4)                         // 128 KB
#define RED_FLOATS (8 * 4 * 32 * 4)                       // 4096 per buffer
#define REC_SMEM_BYTES (W_WORDS * 4 + 2 * RED_FLOATS * 4) // 163840 B

__global__ __launch_bounds__(256, 1) void lstm_rec_kernel(
    const float* __restrict__ carry,   // (16, 1024, 2)
    const float* __restrict__ Wh,      // (1024, 4096)
    const float* __restrict__ bias,    // (4096,)
    float* __restrict__ dout)          // out (16,2048,1024) then carry
{
    extern __shared__ uint32_t sm_w[];              // Wh fragments
    float* red = (float*)(sm_w + W_WORDS);          // [2][w][n][lane][4]

    const int tid  = threadIdx.x;
    const int w    = tid >> 5;
    const int lane = tid & 31;
    const int d0   = blockIdx.x * DPB;

    // ---- pack Wh slice into smem as mma B fragments (hi/lo bf16) ----
    for (int idx = tid; idx < 4 * 64 * 32 * 2; idx += 256) {
        int n    = idx >> 12;
        int rem  = idx & 4095;
        int ks   = rem >> 6;
        int rem2 = rem & 63;
        int ln   = rem2 >> 1;
        int reg  = rem2 & 1;
        int tig  = ln & 3;
        int dl   = ln >> 2;
        int kb   = ks * 16 + reg * 8 + tig * 2;
        size_t col = (size_t)n * DD + d0 + dl;
        float v0 = Wh[(size_t)kb * EE + col];
        float v1 = Wh[(size_t)(kb + 1) * EE + col];
        __nv_bfloat16 h0, l0, h1, l1;
        split_bf16(v0, h0, l0);
        split_bf16(v1, h1, l1);
        uint32_t whi = (uint32_t)__bfloat16_as_ushort(h0) |
                       ((uint32_t)__bfloat16_as_ushort(h1) << 16);
        uint32_t wlo = (uint32_t)__bfloat16_as_ushort(l0) |
                       ((uint32_t)__bfloat16_as_ushort(l1) << 16);
        uint32_t* wp = sm_w + (size_t)(((n * 64 + ks) * 32 + ln)) * 4;
        wp[reg]     = whi;
        wp[2 + reg] = wlo;
    }

    // ---- gate-thread constants + publish h0 ----
    float c_reg = 0.f, h_last = 0.f, bi = 0.f, bf_ = 0.f, bgt = 0.f, bo = 0.f;
    int pb = 0, pd = 0, pdg = 0, lane_c = 0, reg_c = 0;
    unsigned whoff = 0;          // u32 word offset of my (hi,lo) pair
    int even = 0;
    unsigned myflag = (unsigned)(blockIdx.x >> 4);   // producer group

    if (tid < 128) {
        pd  = tid & 7;
        pb  = tid >> 3;
        pdg = d0 + pd;
        int ksp  = pdg >> 4;
        int cc   = pdg & 15;
        int lnp  = (pb & 7) * 4 + ((cc & 7) >> 1);
        int regp = ((pb >> 3) & 1) + 2 * ((cc >> 3) & 1);
        whoff = (unsigned)((ksp * 32 + lnp) * 8 + 2 * regp);
        even  = ((cc & 1) == 0);
        lane_c = (pb & 7) * 4 + (pd >> 1);
        reg_c  = 2 * (pb >> 3) + (pd & 1);

        c_reg = carry[((size_t)pb * DD + pdg) * 2 + 1];
        float h0v = carry[((size_t)pb * DD + pdg) * 2 + 0];
        bi  = bias[pdg];
        bf_ = bias[DD + pdg];
        bgt = bias[2 * DD + pdg];
        bo  = bias[3 * DD + pdg];

        // publish h0 pair (even thread stores both halfwords via shfl)
        __nv_bfloat16 hhi, hlo;
        split_bf16(h0v, hhi, hlo);
        uint32_t v = (uint32_t)__bfloat16_as_ushort(hhi) |
                     ((uint32_t)__bfloat16_as_ushort(hlo) << 16);
        uint32_t pv = __shfl_xor_sync(0xffffffffu, v, 1);
        if (even) {
            uint2 pr;
            pr.x = (v & 0xffffu) | ((pv & 0xffffu) << 16);   // hi word
            pr.y = (v >> 16) | ((pv >> 16) << 16);           // lo word
            *(uint2*)(g_hfrag[0] + whoff) = pr;
        }
        __threadfence();
    }
    __syncthreads();
    if (tid == 0) {
        asm volatile("red.release.gpu.global.add.u32 [%0], %1;"
                     :: "l"(&g_flags[myflag * 64]), "r"(1u) : "memory");
    }

    unsigned* const fp = &g_flags[(unsigned)w * 64];
    float* nc = dout + (size_t)BB * TT * DD;

    for (int t = 0; t < TT; ++t) {
        // xg prefetch (independent of the flag)
        float xgi = 0.f, xgf = 0.f, xgg = 0.f, xgo = 0.f;
        if (tid < 128) {
            const float* xr = g_xg + ((size_t)pb * TT + t) * EE + pdg;
            xgi = __ldg(xr);
            xgf = __ldg(xr + DD);
            xgg = __ldg(xr + 2 * DD);
            xgo = __ldg(xr + 3 * DD);
        }

        // wait for this warp's 16 producer blocks to publish h_t
        {
            const unsigned tgt = (unsigned)(t + 1) * 16u;
            unsigned v;
            do {
                asm volatile("ld.global.acquire.gpu.u32 %0, [%1];"
                             : "=r"(v) : "l"(fp) : "memory");
            } while (v < tgt);
        }

        // MMA over this warp's 8 kslices x 4 ntiles x 3 splits
        float4 acc[4];
#pragma unroll
        for (int n = 0; n < 4; ++n) acc[n] = make_float4(0.f, 0.f, 0.f, 0.f);

        const uint4* ab = (const uint4*)g_hfrag[t & 1];
#pragma unroll
        for (int j = 0; j < 8; ++j) {
            int ks = w * 8 + j;
            uint4 q0 = __ldcg(ab + (ks * 32 + lane) * 2);
            uint4 q1 = __ldcg(ab + (ks * 32 + lane) * 2 + 1);
            uint4 ahi = make_uint4(q0.x, q0.z, q1.x, q1.z);
            uint4 alo = make_uint4(q0.y, q0.w, q1.y, q1.w);
#pragma unroll
            for (int n = 0; n < 4; ++n) {
                uint4 b = *(const uint4*)(sm_w + (size_t)(((n * 64 + ks) * 32 + lane)) * 4);
                mma_bf16(acc[n], ahi, b.x, b.y);   // hi * hi
                mma_bf16(acc[n], ahi, b.z, b.w);   // hi * lo
                mma_bf16(acc[n], alo, b.x, b.y);   // lo * hi
            }
        }

        // partial C -> smem (double buffered by t parity)
        float* rb = red + (t & 1) * RED_FLOATS;
#pragma unroll
        for (int n = 0; n < 4; ++n) {
            *(float4*)(rb + (size_t)(((w * 4 + n) * 32 + lane)) * 4) = acc[n];
        }
        __syncthreads();

        if (tid < 128) {
            float gi = xgi + bi, gf = xgf + bf_, gg = xgg + bgt, go = xgo + bo;
#pragma unroll
            for (int q = 0; q < 8; ++q) {
                const float* rp = rb + (size_t)(q * 4) * 128;
                gi += rp[lane_c * 4 + reg_c];
                gf += rp[128 + lane_c * 4 + reg_c];
                gg += rp[256 + lane_c * 4 + reg_c];
                go += rp[384 + lane_c * 4 + reg_c];
            }
            float iv = fast_sigmoid(gi);
            float fv = fast_sigmoid(gf);
            float gv = fast_tanh(gg);
            float ov = fast_sigmoid(go);
            c_reg    = fv * c_reg + iv * gv;
            float hv = ov * fast_tanh(c_reg);
            h_last   = hv;

            dout[((size_t)pb * TT + t) * DD + pdg] = hv;

            if (t + 1 < TT) {
                __nv_bfloat16 hhi, hlo;
                split_bf16(hv, hhi, hlo);
                uint32_t v = (uint32_t)__bfloat16_as_ushort(hhi) |
                             ((uint32_t)__bfloat16_as_ushort(hlo) << 16);
                uint32_t pv = __shfl_xor_sync(0xffffffffu, v, 1);
                if (even) {
                    uint2 pr;
                    pr.x = (v & 0xffffu) | ((pv & 0xffffu) << 16);
                    pr.y = (v >> 16) | ((pv >> 16) << 16);
                    *(uint2*)(g_hfrag[(t + 1) & 1] + whoff) = pr;
                }
                __threadfence();
                asm volatile("bar.sync 1, 128;" ::: "memory");
                if (tid == 0) {
                    asm volatile("red.release.gpu.global.add.u32 [%0], %1;"
                                 :: "l"(&g_flags[myflag * 64]), "r"(1u)
                                 : "memory");
                }
            }
        }
    }

    // final carry
    if (tid < 128) {
        nc[((size_t)pb * DD + pdg) * 2 + 0] = h_last;
        nc[((size_t)pb * DD + pdg) * 2 + 1] = c_reg;
    }

    // last block to finish resets the flags for the next graph replay
    __syncthreads();
    if (tid == 0) {
        __threadfence();
        unsigned r = atomicAdd(&g_endcnt, 1u);
        if ((r & 127u) == 127u) {
#pragma unroll
            for (int g = 0; g < 8; ++g) g_flags[g * 64] = 0u;
            __threadfence();
        }
    }
}

// ---------------------------------------------------------------------------
// Launch
// ---------------------------------------------------------------------------
extern "C" void kernel_launch(void* const* d_in, const int* in_sizes, int n_in,
                              void* d_out, int out_size) {
    (void)in_sizes; (void)n_in; (void)out_size;
    const float* x     = (const float*)d_in[0];
    const float* carry = (const float*)d_in[1];
    const float* Wi    = (const float*)d_in[2];
    const float* Wh    = (const float*)d_in[3];
    const float* b     = (const float*)d_in[4];
    float* out = (float*)d_out;

    dim3 ggrid(EE / 128, (BB * TT) / 128);
    gemm_xg_kernel<<<ggrid, 256>>>(x, Wi);

    cudaFuncSetAttribute(lstm_rec_kernel,
                         cudaFuncAttributeMaxDynamicSharedMemorySize,
                         REC_SMEM_BYTES);
    lstm_rec_kernel<<<REC_BLOCKS, 256, REC_SMEM_BYTES>>>(carry, Wh, b, out);
}

// round 4
// speedup vs baseline: 2.1604x; 1.4618x over previous
#include <cuda_runtime.h>
#include <cuda_bf16.h>
#include <cstdint>
#include <cstddef>

// Problem constants: B=16, T=2048, D=1024, E=4D=4096
#define BB 16
#define TT 2048
#define DD 1024
#define EE 4096

#define REC_BLOCKS 128
#define DPB (DD / REC_BLOCKS)

// ---------------------------------------------------------------------------
// Device scratch
// ---------------------------------------------------------------------------
__device__ float g_xg[(size_t)BB * TT * EE];

// h in mma A-fragment order, hi/lo interleaved per register:
// word index = (ks*32 + lane)*8 + 2*reg + {0:hi, 1:lo}.  64 KB per buffer.
__device__ __align__(16) uint32_t g_hfrag[2][64 * 32 * 8];

__device__ unsigned g_flags[8 * 64];
__device__ unsigned g_endcnt;

// ---------------------------------------------------------------------------
// MMA helpers
// ---------------------------------------------------------------------------
__device__ __forceinline__ void mma4(float* c, const uint32_t* a,
                                     uint32_t b0, uint32_t b1) {
    asm volatile(
        "mma.sync.aligned.m16n8k16.row.col.f32.bf16.bf16.f32 "
        "{%0,%1,%2,%3}, {%4,%5,%6,%7}, {%8,%9}, {%0,%1,%2,%3};\n"
        : "+f"(c[0]), "+f"(c[1]), "+f"(c[2]), "+f"(c[3])
        : "r"(a[0]), "r"(a[1]), "r"(a[2]), "r"(a[3]), "r"(b0), "r"(b1));
}

__device__ __forceinline__ void mma_bf16(float4& c, const uint4& a,
                                         uint32_t b0, uint32_t b1) {
    asm volatile(
        "mma.sync.aligned.m16n8k16.row.col.f32.bf16.bf16.f32 "
        "{%0,%1,%2,%3}, {%4,%5,%6,%7}, {%8,%9}, {%0,%1,%2,%3};\n"
        : "+f"(c.x), "+f"(c.y), "+f"(c.z), "+f"(c.w)
        : "r"(a.x), "r"(a.y), "r"(a.z), "r"(a.w), "r"(b0), "r"(b1));
}

__device__ __forceinline__ void ldsm_x4(uint32_t* r, uint32_t addr) {
    asm volatile("ldmatrix.sync.aligned.m8n8.x4.shared.b16 {%0,%1,%2,%3}, [%4];"
        : "=r"(r[0]), "=r"(r[1]), "=r"(r[2]), "=r"(r[3]) : "r"(addr));
}
__device__ __forceinline__ void ldsm_x4_t(uint32_t* r, uint32_t addr) {
    asm volatile("ldmatrix.sync.aligned.m8n8.x4.trans.shared.b16 {%0,%1,%2,%3}, [%4];"
        : "=r"(r[0]), "=r"(r[1]), "=r"(r[2]), "=r"(r[3]) : "r"(addr));
}

__device__ __forceinline__ void split_bf16(float v, __nv_bfloat16& hi,
                                           __nv_bfloat16& lo) {
    hi = __float2bfloat16(v);
    lo = __float2bfloat16(v - __bfloat162float(hi));
}

__device__ __forceinline__ float fast_sigmoid(float x) {
    return __fdividef(1.f, 1.f + __expf(-x));
}
__device__ __forceinline__ float fast_tanh(float x) {
    return __fdividef(2.f, 1.f + __expf(-2.f * x)) - 1.f;
}

// ---------------------------------------------------------------------------
// Phase 1: xg = x @ Wi via 3-pass bf16-split tensor-core MMA.
// BM=128, BN=128, BK=32; 256 threads; warp tile 32(m) x 64(n).
// smem (dynamic): A hi/lo [2 stages][128][40] bf16 + B hi/lo [2][32][136].
// ---------------------------------------------------------------------------
#define A_STRIDE 40    // bf16 elems per A row (32 + 8 pad) -> 80 B
#define B_STRIDE 136   // bf16 elems per B k-row (128 + 8 pad) -> 272 B
#define A_PLANE (128 * A_STRIDE)        // elems
#define B_PLANE (32 * B_STRIDE)
#define GEMM_SMEM_BYTES ((4 * A_PLANE + 4 * B_PLANE) * 2)   // 75776 B

__device__ __forceinline__ uint32_t pack_bf2(__nv_bfloat16 a, __nv_bfloat16 b) {
    return (uint32_t)__bfloat16_as_ushort(a) |
           ((uint32_t)__bfloat16_as_ushort(b) << 16);
}

__global__ __launch_bounds__(256) void gemm_xg_mma(
    const float* __restrict__ A,    // x   (32768 x 1024)
    const float* __restrict__ W)    // Wi  (1024 x 4096)
{
    extern __shared__ __align__(16) __nv_bfloat16 gsm[];
    __nv_bfloat16* const asB = gsm;                 // 4 planes of A_PLANE
    __nv_bfloat16* const bsB = gsm + 4 * A_PLANE;   // 4 planes of B_PLANE

    const int tid  = threadIdx.x;
    const int lane = tid & 31;
    const int w    = tid >> 5;
    const int wn   = w >> 2;     // 0..1
    const int wm   = w & 3;      // 0..3
    const int m0   = blockIdx.y * 128;
    const int n0   = blockIdx.x * 128;

    // fill mappings
    const int arow = tid >> 3;          // + 32*j
    const int acf4 = tid & 7;
    const int bkr  = tid >> 5;          // + 8*j
    const int bnf4 = tid & 31;

    const float* aP = A + (size_t)(m0 + arow) * DD + acf4 * 4;
    const float* bP = W + (size_t)bkr * EE + n0 + bnf4 * 4;

    float4 aR[4], bR[4];
#pragma unroll
    for (int j = 0; j < 4; ++j) {
        aR[j] = *(const float4*)(aP + (size_t)32 * j * DD);
        bR[j] = *(const float4*)(bP + (size_t)8 * j * EE);
    }

    float acc[2][8][4];
#pragma unroll
    for (int mt = 0; mt < 2; ++mt)
#pragma unroll
        for (int nt = 0; nt < 8; ++nt)
#pragma unroll
            for (int i = 0; i < 4; ++i) acc[mt][nt][i] = 0.f;

    const uint32_t smem_u32 = (uint32_t)__cvta_generic_to_shared(gsm);

    int stage = 0;
    for (int it = 0; it < 32; ++it) {
        __nv_bfloat16* ah = asB + (stage * 2 + 0) * A_PLANE;
        __nv_bfloat16* al = asB + (stage * 2 + 1) * A_PLANE;
        __nv_bfloat16* bh = bsB + (stage * 2 + 0) * B_PLANE;
        __nv_bfloat16* bl = bsB + (stage * 2 + 1) * B_PLANE;

#pragma unroll
        for (int j = 0; j < 4; ++j) {
            // A
            {
                int row = arow + 32 * j;
                float v[4] = {aR[j].x, aR[j].y, aR[j].z, aR[j].w};
                __nv_bfloat16 h[4], l[4];
#pragma unroll
                for (int q = 0; q < 4; ++q) split_bf16(v[q], h[q], l[q]);
                *(uint2*)(ah + row * A_STRIDE + acf4 * 4) =
                    make_uint2(pack_bf2(h[0], h[1]), pack_bf2(h[2], h[3]));
                *(uint2*)(al + row * A_STRIDE + acf4 * 4) =
                    make_uint2(pack_bf2(l[0], l[1]), pack_bf2(l[2], l[3]));
            }
            // B
            {
                int krow = bkr + 8 * j;
                float v[4] = {bR[j].x, bR[j].y, bR[j].z, bR[j].w};
                __nv_bfloat16 h[4], l[4];
#pragma unroll
                for (int q = 0; q < 4; ++q) split_bf16(v[q], h[q], l[q]);
                *(uint2*)(bh + krow * B_STRIDE + bnf4 * 4) =
                    make_uint2(pack_bf2(h[0], h[1]), pack_bf2(h[2], h[3]));
                *(uint2*)(bl + krow * B_STRIDE + bnf4 * 4) =
                    make_uint2(pack_bf2(l[0], l[1]), pack_bf2(l[2], l[3]));
            }
        }
        __syncthreads();

        if (it < 31) {
            const float* aN = aP + (it + 1) * 32;
            const float* bN = bP + (size_t)(it + 1) * 32 * EE;
#pragma unroll
            for (int j = 0; j < 4; ++j) {
                aR[j] = *(const float4*)(aN + (size_t)32 * j * DD);
                bR[j] = *(const float4*)(bN + (size_t)8 * j * EE);
            }
        }

        const uint32_t aBase = smem_u32 + (stage * 2) * (A_PLANE * 2);
        const uint32_t bBase = smem_u32 + 4 * A_PLANE * 2 + (stage * 2) * (B_PLANE * 2);

#pragma unroll
        for (int ks = 0; ks < 2; ++ks) {
            uint32_t afr[2][2][4];
#pragma unroll
            for (int mt = 0; mt < 2; ++mt)
#pragma unroll
                for (int p = 0; p < 2; ++p) {
                    uint32_t addr = aBase + p * (A_PLANE * 2)
                        + (uint32_t)((wm * 32 + mt * 16 + (lane & 15)) * (A_STRIDE * 2))
                        + (uint32_t)((ks * 16 + (lane >> 4) * 8) * 2);
                    ldsm_x4(afr[mt][p], addr);
                }
            uint32_t bfr[4][2][4];
#pragma unroll
            for (int np = 0; np < 4; ++np)
#pragma unroll
                for (int p = 0; p < 2; ++p) {
                    uint32_t addr = bBase + p * (B_PLANE * 2)
                        + (uint32_t)((ks * 16 + (lane & 15)) * (B_STRIDE * 2))
                        + (uint32_t)((wn * 64 + np * 16 + (lane >> 4) * 8) * 2);
                    ldsm_x4_t(bfr[np][p], addr);
                }
#pragma unroll
            for (int mt = 0; mt < 2; ++mt)
#pragma unroll
                for (int np = 0; np < 4; ++np)
#pragma unroll
                    for (int hf = 0; hf < 2; ++hf) {
                        int nt = np * 2 + hf;
                        float* c = acc[mt][nt];
                        uint32_t bh0 = bfr[np][0][hf * 2];
                        uint32_t bh1 = bfr[np][0][hf * 2 + 1];
                        uint32_t bl0 = bfr[np][1][hf * 2];
                        uint32_t bl1 = bfr[np][1][hf * 2 + 1];
                        mma4(c, afr[mt][0], bh0, bh1);   // hi*hi
                        mma4(c, afr[mt][0], bl0, bl1);   // hi*lo
                        mma4(c, afr[mt][1], bh0, bh1);   // lo*hi
                    }
        }
        stage ^= 1;
    }

    // epilogue
#pragma unroll
    for (int mt = 0; mt < 2; ++mt)
#pragma unroll
        for (int nt = 0; nt < 8; ++nt) {
            int row = m0 + wm * 32 + mt * 16 + (lane >> 2);
            int col = n0 + wn * 64 + nt * 8 + (lane & 3) * 2;
            float* c = acc[mt][nt];
            *(float2*)(g_xg + (size_t)row * EE + col)       = make_float2(c[0], c[1]);
            *(float2*)(g_xg + (size_t)(row + 8) * EE + col) = make_float2(c[2], c[3]);
        }
}

// ---------------------------------------------------------------------------
// Phase 2: persistent recurrence (bf16x2-split MMA + fine-grained flags).
// Changes vs R3: no __threadfence (bar.sync + red.release.gpu transitivity),
// publish h_{t+1} BEFORE the dout store.
// ---------------------------------------------------------------------------
#define W_WORDS (4 * 64 * 32 * 4)
#define RED_FLOATS (8 * 4 * 32 * 4)
#define REC_SMEM_BYTES (W_WORDS * 4 + 2 * RED_FLOATS * 4)

__global__ __launch_bounds__(256, 1) void lstm_rec_kernel(
    const float* __restrict__ carry,
    const float* __restrict__ Wh,
    const float* __restrict__ bias,
    float* __restrict__ dout)
{
    extern __shared__ uint32_t sm_w[];
    float* red = (float*)(sm_w + W_WORDS);

    const int tid  = threadIdx.x;
    const int w    = tid >> 5;
    const int lane = tid & 31;
    const int d0   = blockIdx.x * DPB;

    // pack Wh slice into smem as mma B fragments (hi/lo bf16)
    for (int idx = tid; idx < 4 * 64 * 32 * 2; idx += 256) {
        int n    = idx >> 12;
        int rem  = idx & 4095;
        int ks   = rem >> 6;
        int rem2 = rem & 63;
        int ln   = rem2 >> 1;
        int reg  = rem2 & 1;
        int tig  = ln & 3;
        int dl   = ln >> 2;
        int kb   = ks * 16 + reg * 8 + tig * 2;
        size_t col = (size_t)n * DD + d0 + dl;
        float v0 = Wh[(size_t)kb * EE + col];
        float v1 = Wh[(size_t)(kb + 1) * EE + col];
        __nv_bfloat16 h0, l0, h1, l1;
        split_bf16(v0, h0, l0);
        split_bf16(v1, h1, l1);
        uint32_t* wp = sm_w + (size_t)(((n * 64 + ks) * 32 + ln)) * 4;
        wp[reg]     = pack_bf2(h0, h1);
        wp[2 + reg] = pack_bf2(l0, l1);
    }

    float c_reg = 0.f, h_last = 0.f, bi = 0.f, bf_ = 0.f, bgt = 0.f, bo = 0.f;
    int pb = 0, pd = 0, pdg = 0, lane_c = 0, reg_c = 0;
    unsigned whoff = 0;
    int even = 0;
    unsigned myflag = (unsigned)(blockIdx.x >> 4);

    if (tid < 128) {
        pd  = tid & 7;
        pb  = tid >> 3;
        pdg = d0 + pd;
        int ksp  = pdg >> 4;
        int cc   = pdg & 15;
        int lnp  = (pb & 7) * 4 + ((cc & 7) >> 1);
        int regp = ((pb >> 3) & 1) + 2 * ((cc >> 3) & 1);
        whoff = (unsigned)((ksp * 32 + lnp) * 8 + 2 * regp);
        even  = ((cc & 1) == 0);
        lane_c = (pb & 7) * 4 + (pd >> 1);
        reg_c  = 2 * (pb >> 3) + (pd & 1);

        c_reg = carry[((size_t)pb * DD + pdg) * 2 + 1];
        float h0v = carry[((size_t)pb * DD + pdg) * 2 + 0];
        bi  = bias[pdg];
        bf_ = bias[DD + pdg];
        bgt = bias[2 * DD + pdg];
        bo  = bias[3 * DD + pdg];

        __nv_bfloat16 hhi, hlo;
        split_bf16(h0v, hhi, hlo);
        uint32_t v  = pack_bf2(hhi, hlo);
        uint32_t pv = __shfl_xor_sync(0xffffffffu, v, 1);
        if (even) {
            uint2 pr;
            pr.x = (v & 0xffffu) | ((pv & 0xffffu) << 16);
            pr.y = (v >> 16) | ((pv >> 16) << 16);
            *(uint2*)(g_hfrag[0] + whoff) = pr;
        }
    }
    __syncthreads();
    if (tid == 0) {
        asm volatile("red.release.gpu.global.add.u32 [%0], %1;"
                     :: "l"(&g_flags[myflag * 64]), "r"(1u) : "memory");
    }

    unsigned* const fp = &g_flags[(unsigned)w * 64];
    float* nc = dout + (size_t)BB * TT * DD;

    for (int t = 0; t < TT; ++t) {
        float xgi = 0.f, xgf = 0.f, xgg = 0.f, xgo = 0.f;
        if (tid < 128) {
            const float* xr = g_xg + ((size_t)pb * TT + t) * EE + pdg;
            xgi = __ldg(xr);
            xgf = __ldg(xr + DD);
            xgg = __ldg(xr + 2 * DD);
            xgo = __ldg(xr + 3 * DD);
        }

        {
            const unsigned tgt = (unsigned)(t + 1) * 16u;
            unsigned v;
            do {
                asm volatile("ld.global.acquire.gpu.u32 %0, [%1];"
                             : "=r"(v) : "l"(fp) : "memory");
            } while (v < tgt);
        }

        float4 acc[4];
#pragma unroll
        for (int n = 0; n < 4; ++n) acc[n] = make_float4(0.f, 0.f, 0.f, 0.f);

        const uint4* ab = (const uint4*)g_hfrag[t & 1];
#pragma unroll
        for (int j = 0; j < 8; ++j) {
            int ks = w * 8 + j;
            uint4 q0 = __ldcg(ab + (ks * 32 + lane) * 2);
            uint4 q1 = __ldcg(ab + (ks * 32 + lane) * 2 + 1);
            uint4 ahi = make_uint4(q0.x, q0.z, q1.x, q1.z);
            uint4 alo = make_uint4(q0.y, q0.w, q1.y, q1.w);
#pragma unroll
            for (int n = 0; n < 4; ++n) {
                uint4 b = *(const uint4*)(sm_w + (size_t)(((n * 64 + ks) * 32 + lane)) * 4);
                mma_bf16(acc[n], ahi, b.x, b.y);
                mma_bf16(acc[n], ahi, b.z, b.w);
                mma_bf16(acc[n], alo, b.x, b.y);
            }
        }

        float* rb = red + (t & 1) * RED_FLOATS;
#pragma unroll
        for (int n = 0; n < 4; ++n) {
            *(float4*)(rb + (size_t)(((w * 4 + n) * 32 + lane)) * 4) = acc[n];
        }
        __syncthreads();

        if (tid < 128) {
            float gi = xgi + bi, gf = xgf + bf_, gg = xgg + bgt, go = xgo + bo;
#pragma unroll
            for (int q = 0; q < 8; ++q) {
                const float* rp = rb + (size_t)(q * 4) * 128;
                gi += rp[lane_c * 4 + reg_c];
                gf += rp[128 + lane_c * 4 + reg_c];
                gg += rp[256 + lane_c * 4 + reg_c];
                go += rp[384 + lane_c * 4 + reg_c];
            }
            float iv = fast_sigmoid(gi);
            float fv = fast_sigmoid(gf);
            float gv = fast_tanh(gg);
            float ov = fast_sigmoid(go);
            c_reg    = fv * c_reg + iv * gv;
            float hv = ov * fast_tanh(c_reg);
            h_last   = hv;

            // publish FIRST (inter-block critical path), then dout
            if (t + 1 < TT) {
                __nv_bfloat16 hhi, hlo;
                split_bf16(hv, hhi, hlo);
                uint32_t v  = pack_bf2(hhi, hlo);
                uint32_t pv = __shfl_xor_sync(0xffffffffu, v, 1);
                if (even) {
                    uint2 pr;
                    pr.x = (v & 0xffffu) | ((pv & 0xffffu) << 16);
                    pr.y = (v >> 16) | ((pv >> 16) << 16);
                    *(uint2*)(g_hfrag[(t + 1) & 1] + whoff) = pr;
                }
                asm volatile("bar.sync 1, 128;" ::: "memory");
                if (tid == 0) {
                    asm volatile("red.release.gpu.global.add.u32 [%0], %1;"
                                 :: "l"(&g_flags[myflag * 64]), "r"(1u)
                                 : "memory");
                }
            }
            dout[((size_t)pb * TT + t) * DD + pdg] = hv;
        }
    }

    if (tid < 128) {
        nc[((size_t)pb * DD + pdg) * 2 + 0] = h_last;
        nc[((size_t)pb * DD + pdg) * 2 + 1] = c_reg;
    }

    __syncthreads();
    if (tid == 0) {
        __threadfence();
        unsigned r = atomicAdd(&g_endcnt, 1u);
        if ((r & 127u) == 127u) {
#pragma unroll
            for (int g = 0; g < 8; ++g) g_flags[g * 64] = 0u;
            __threadfence();
        }
    }
}

// ---------------------------------------------------------------------------
// Launch
// ---------------------------------------------------------------------------
extern "C" void kernel_launch(void* const* d_in, const int* in_sizes, int n_in,
                              void* d_out, int out_size) {
    (void)in_sizes; (void)n_in; (void)out_size;
    const float* x     = (const float*)d_in[0];
    const float* carry = (const float*)d_in[1];
    const float* Wi    = (const float*)d_in[2];
    const float* Wh    = (const float*)d_in[3];
    const float* b     = (const float*)d_in[4];
    float* out = (float*)d_out;

    cudaFuncSetAttribute(gemm_xg_mma,
                         cudaFuncAttributeMaxDynamicSharedMemorySize,
                         GEMM_SMEM_BYTES);
    dim3 ggrid(EE / 128, (BB * TT) / 128);
    gemm_xg_mma<<<ggrid, 256, GEMM_SMEM_BYTES>>>(x, Wi);

    cudaFuncSetAttribute(lstm_rec_kernel,
                         cudaFuncAttributeMaxDynamicSharedMemorySize,
                         REC_SMEM_BYTES);
    lstm_rec_kernel<<<REC_BLOCKS, 256, REC_SMEM_BYTES>>>(carry, Wh, b, out);
}

// round 5
// speedup vs baseline: 2.2919x; 1.0609x over previous
#include <cuda_runtime.h>
#include <cuda_bf16.h>
#include <cstdint>
#include <cstddef>

// Problem constants: B=16, T=2048, D=1024, E=4D=4096
#define BB 16
#define TT 2048
#define DD 1024
#define EE 4096

#define REC_BLOCKS 128
#define DPB (DD / REC_BLOCKS)

// ---------------------------------------------------------------------------
// Device scratch
// ---------------------------------------------------------------------------
__device__ float g_xg[(size_t)BB * TT * EE];

__device__ __nv_bfloat16 g_xhi[(size_t)BB * TT * DD];
__device__ __nv_bfloat16 g_xlo[(size_t)BB * TT * DD];
__device__ __nv_bfloat16 g_wihi[(size_t)DD * EE];
__device__ __nv_bfloat16 g_wilo[(size_t)DD * EE];

// h in mma A-fragment order, hi/lo interleaved per register.
__device__ __align__(16) uint32_t g_hfrag[2][64 * 32 * 8];

__device__ unsigned g_flags[8 * 64];
__device__ unsigned g_endcnt;

// ---------------------------------------------------------------------------
// Helpers
// ---------------------------------------------------------------------------
__device__ __forceinline__ void mma4(float* c, const uint32_t* a,
                                     uint32_t b0, uint32_t b1) {
    asm volatile(
        "mma.sync.aligned.m16n8k16.row.col.f32.bf16.bf16.f32 "
        "{%0,%1,%2,%3}, {%4,%5,%6,%7}, {%8,%9}, {%0,%1,%2,%3};\n"
        : "+f"(c[0]), "+f"(c[1]), "+f"(c[2]), "+f"(c[3])
        : "r"(a[0]), "r"(a[1]), "r"(a[2]), "r"(a[3]), "r"(b0), "r"(b1));
}

__device__ __forceinline__ void mma_bf16(float4& c, const uint4& a,
                                         uint32_t b0, uint32_t b1) {
    asm volatile(
        "mma.sync.aligned.m16n8k16.row.col.f32.bf16.bf16.f32 "
        "{%0,%1,%2,%3}, {%4,%5,%6,%7}, {%8,%9}, {%0,%1,%2,%3};\n"
        : "+f"(c.x), "+f"(c.y), "+f"(c.z), "+f"(c.w)
        : "r"(a.x), "r"(a.y), "r"(a.z), "r"(a.w), "r"(b0), "r"(b1));
}

__device__ __forceinline__ void ldsm_x4(uint32_t* r, uint32_t addr) {
    asm volatile("ldmatrix.sync.aligned.m8n8.x4.shared.b16 {%0,%1,%2,%3}, [%4];"
        : "=r"(r[0]), "=r"(r[1]), "=r"(r[2]), "=r"(r[3]) : "r"(addr));
}
__device__ __forceinline__ void ldsm_x4_t(uint32_t* r, uint32_t addr) {
    asm volatile("ldmatrix.sync.aligned.m8n8.x4.trans.shared.b16 {%0,%1,%2,%3}, [%4];"
        : "=r"(r[0]), "=r"(r[1]), "=r"(r[2]), "=r"(r[3]) : "r"(addr));
}

__device__ __forceinline__ void split_bf16(float v, __nv_bfloat16& hi,
                                           __nv_bfloat16& lo) {
    hi = __float2bfloat16(v);
    lo = __float2bfloat16(v - __bfloat162float(hi));
}

__device__ __forceinline__ uint32_t pack_bf2(__nv_bfloat16 a, __nv_bfloat16 b) {
    return (uint32_t)__bfloat16_as_ushort(a) |
           ((uint32_t)__bfloat16_as_ushort(b) << 16);
}

__device__ __forceinline__ float fast_sigmoid(float x) {
    return __fdividef(1.f, 1.f + __expf(-x));
}
__device__ __forceinline__ float fast_tanh(float x) {
    return __fdividef(2.f, 1.f + __expf(-2.f * x)) - 1.f;
}

#define CP_ASYNC16(dst, src) \
    asm volatile("cp.async.cg.shared.global [%0], [%1], 16;" \
                 :: "r"(dst), "l"(src))
#define CP_COMMIT() asm volatile("cp.async.commit_group;" ::: "memory")
#define CP_WAIT2()  asm volatile("cp.async.wait_group 2;" ::: "memory")

// ---------------------------------------------------------------------------
// Phase 0: split fp32 -> bf16 hi/lo planes
// ---------------------------------------------------------------------------
__global__ __launch_bounds__(256) void split_kernel(
    const float* __restrict__ src,
    __nv_bfloat16* __restrict__ hi,
    __nv_bfloat16* __restrict__ lo,
    size_t n4)
{
    size_t i = (size_t)blockIdx.x * 256 + threadIdx.x;
    if (i >= n4) return;
    float4 v = ((const float4*)src)[i];
    __nv_bfloat16 h[4], l[4];
    split_bf16(v.x, h[0], l[0]);
    split_bf16(v.y, h[1], l[1]);
    split_bf16(v.z, h[2], l[2]);
    split_bf16(v.w, h[3], l[3]);
    ((uint2*)hi)[i] = make_uint2(pack_bf2(h[0], h[1]), pack_bf2(h[2], h[3]));
    ((uint2*)lo)[i] = make_uint2(pack_bf2(l[0], l[1]), pack_bf2(l[2], l[3]));
}

// ---------------------------------------------------------------------------
// Phase 1: xg = x @ Wi via 3-pass bf16 MMA, cp.async 3-stage pipeline.
// BM=128, BN=128, BK=32; 256 threads; warp tile 32(m) x 64(n).
// ---------------------------------------------------------------------------
#define A_STRIDE 40          // bf16 elems per A row (32 + 8 pad)
#define B_STRIDE 136         // bf16 elems per B k-row (128 + 8 pad)
#define A_PLANE (128 * A_STRIDE)
#define B_PLANE (32 * B_STRIDE)
#define STAGE_ELEMS (2 * A_PLANE + 2 * B_PLANE)
#define STAGE_BYTES (STAGE_ELEMS * 2)
#define GEMM_SMEM_BYTES (3 * STAGE_BYTES)      // 113664 B

__global__ __launch_bounds__(256) void gemm_xg_mma(void)
{
    extern __shared__ __align__(16) __nv_bfloat16 gsm[];

    const int tid  = threadIdx.x;
    const int lane = tid & 31;
    const int w    = tid >> 5;
    const int wn   = w >> 2;     // 0..1
    const int wm   = w & 3;      // 0..3
    const int m0   = blockIdx.y * 128;
    const int n0   = blockIdx.x * 128;

    const uint32_t smem_u32 = (uint32_t)__cvta_generic_to_shared(gsm);

    // cp.async fill for one stage / k-tile
    auto issue_stage = [&](int stage, int kt) {
        const int k0 = kt * 32;
        uint32_t sb = smem_u32 + stage * STAGE_BYTES;
        // A planes: 512 chunks of 16 B each
#pragma unroll
        for (int r = 0; r < 2; ++r) {
            int chunk = tid + 256 * r;
            int row   = chunk >> 2;
            int c8    = (chunk & 3) * 8;       // elem offset
            const __nv_bfloat16* sh = g_xhi + (size_t)(m0 + row) * DD + k0 + c8;
            const __nv_bfloat16* sl = g_xlo + (size_t)(m0 + row) * DD + k0 + c8;
            uint32_t dh = sb + (uint32_t)(row * A_STRIDE + c8) * 2;
            uint32_t dl = dh + A_PLANE * 2;
            CP_ASYNC16(dh, sh);
            CP_ASYNC16(dl, sl);
        }
        // B planes: 512 chunks
        uint32_t bb = sb + 4 * A_PLANE;        // bytes (2 planes * A_PLANE*2B)
#pragma unroll
        for (int r = 0; r < 2; ++r) {
            int chunk = tid + 256 * r;
            int row   = chunk >> 4;
            int c8    = (chunk & 15) * 8;
            const __nv_bfloat16* sh = g_wihi + (size_t)(k0 + row) * EE + n0 + c8;
            const __nv_bfloat16* sl = g_wilo + (size_t)(k0 + row) * EE + n0 + c8;
            uint32_t dh = bb + (uint32_t)(row * B_STRIDE + c8) * 2;
            uint32_t dl = dh + B_PLANE * 2;
            CP_ASYNC16(dh, sh);
            CP_ASYNC16(dl, sl);
        }
    };

    float acc[2][8][4];
#pragma unroll
    for (int mt = 0; mt < 2; ++mt)
#pragma unroll
        for (int nt = 0; nt < 8; ++nt)
#pragma unroll
            for (int i = 0; i < 4; ++i) acc[mt][nt][i] = 0.f;

    issue_stage(0, 0); CP_COMMIT();
    issue_stage(1, 1); CP_COMMIT();
    issue_stage(2, 2); CP_COMMIT();

    for (int it = 0; it < 32; ++it) {
        CP_WAIT2();
        __syncthreads();

        const int stage = it % 3;
        const uint32_t aBase = smem_u32 + stage * STAGE_BYTES;
        const uint32_t bBase = aBase + 4 * A_PLANE;

#pragma unroll
        for (int ks = 0; ks < 2; ++ks) {
            uint32_t afr[2][2][4];
#pragma unroll
            for (int mt = 0; mt < 2; ++mt)
#pragma unroll
                for (int p = 0; p < 2; ++p) {
                    uint32_t addr = aBase + p * (A_PLANE * 2)
                        + (uint32_t)((wm * 32 + mt * 16 + (lane & 15)) * (A_STRIDE * 2))
                        + (uint32_t)((ks * 16 + (lane >> 4) * 8) * 2);
                    ldsm_x4(afr[mt][p], addr);
                }
            uint32_t bfr[4][2][4];
#pragma unroll
            for (int np = 0; np < 4; ++np)
#pragma unroll
                for (int p = 0; p < 2; ++p) {
                    uint32_t addr = bBase + p * (B_PLANE * 2)
                        + (uint32_t)((ks * 16 + (lane & 15)) * (B_STRIDE * 2))
                        + (uint32_t)((wn * 64 + np * 16 + (lane >> 4) * 8) * 2);
                    ldsm_x4_t(bfr[np][p], addr);
                }
#pragma unroll
            for (int mt = 0; mt < 2; ++mt)
#pragma unroll
                for (int np = 0; np < 4; ++np)
#pragma unroll
                    for (int hf = 0; hf < 2; ++hf) {
                        int nt = np * 2 + hf;
                        float* c = acc[mt][nt];
                        uint32_t bh0 = bfr[np][0][hf * 2];
                        uint32_t bh1 = bfr[np][0][hf * 2 + 1];
                        uint32_t bl0 = bfr[np][1][hf * 2];
                        uint32_t bl1 = bfr[np][1][hf * 2 + 1];
                        mma4(c, afr[mt][0], bh0, bh1);   // hi*hi
                        mma4(c, afr[mt][0], bl0, bl1);   // hi*lo
                        mma4(c, afr[mt][1], bh0, bh1);   // lo*hi
                    }
        }
        __syncthreads();
        if (it + 3 < 32) issue_stage(stage, it + 3);
        CP_COMMIT();
    }

    // epilogue (streaming stores: don't pollute L2)
#pragma unroll
    for (int mt = 0; mt < 2; ++mt)
#pragma unroll
        for (int nt = 0; nt < 8; ++nt) {
            int row = m0 + wm * 32 + mt * 16 + (lane >> 2);
            int col = n0 + wn * 64 + nt * 8 + (lane & 3) * 2;
            float* c = acc[mt][nt];
            __stcs((float2*)(g_xg + (size_t)row * EE + col),
                   make_float2(c[0], c[1]));
            __stcs((float2*)(g_xg + (size_t)(row + 8) * EE + col),
                   make_float2(c[2], c[3]));
        }
}

// ---------------------------------------------------------------------------
// Phase 2: persistent recurrence (unchanged from R4)
// ---------------------------------------------------------------------------
#define W_WORDS (4 * 64 * 32 * 4)
#define RED_FLOATS (8 * 4 * 32 * 4)
#define REC_SMEM_BYTES (W_WORDS * 4 + 2 * RED_FLOATS * 4)

__global__ __launch_bounds__(256, 1) void lstm_rec_kernel(
    const float* __restrict__ carry,
    const float* __restrict__ Wh,
    const float* __restrict__ bias,
    float* __restrict__ dout)
{
    extern __shared__ uint32_t sm_w[];
    float* red = (float*)(sm_w + W_WORDS);

    const int tid  = threadIdx.x;
    const int w    = tid >> 5;
    const int lane = tid & 31;
    const int d0   = blockIdx.x * DPB;

    for (int idx = tid; idx < 4 * 64 * 32 * 2; idx += 256) {
        int n    = idx >> 12;
        int rem  = idx & 4095;
        int ks   = rem >> 6;
        int rem2 = rem & 63;
        int ln   = rem2 >> 1;
        int reg  = rem2 & 1;
        int tig  = ln & 3;
        int dl   = ln >> 2;
        int kb   = ks * 16 + reg * 8 + tig * 2;
        size_t col = (size_t)n * DD + d0 + dl;
        float v0 = Wh[(size_t)kb * EE + col];
        float v1 = Wh[(size_t)(kb + 1) * EE + col];
        __nv_bfloat16 h0, l0, h1, l1;
        split_bf16(v0, h0, l0);
        split_bf16(v1, h1, l1);
        uint32_t* wp = sm_w + (size_t)(((n * 64 + ks) * 32 + ln)) * 4;
        wp[reg]     = pack_bf2(h0, h1);
        wp[2 + reg] = pack_bf2(l0, l1);
    }

    float c_reg = 0.f, h_last = 0.f, bi = 0.f, bf_ = 0.f, bgt = 0.f, bo = 0.f;
    int pb = 0, pd = 0, pdg = 0, lane_c = 0, reg_c = 0;
    unsigned whoff = 0;
    int even = 0;
    unsigned myflag = (unsigned)(blockIdx.x >> 4);

    if (tid < 128) {
        pd  = tid & 7;
        pb  = tid >> 3;
        pdg = d0 + pd;
        int ksp  = pdg >> 4;
        int cc   = pdg & 15;
        int lnp  = (pb & 7) * 4 + ((cc & 7) >> 1);
        int regp = ((pb >> 3) & 1) + 2 * ((cc >> 3) & 1);
        whoff = (unsigned)((ksp * 32 + lnp) * 8 + 2 * regp);
        even  = ((cc & 1) == 0);
        lane_c = (pb & 7) * 4 + (pd >> 1);
        reg_c  = 2 * (pb >> 3) + (pd & 1);

        c_reg = carry[((size_t)pb * DD + pdg) * 2 + 1];
        float h0v = carry[((size_t)pb * DD + pdg) * 2 + 0];
        bi  = bias[pdg];
        bf_ = bias[DD + pdg];
        bgt = bias[2 * DD + pdg];
        bo  = bias[3 * DD + pdg];

        __nv_bfloat16 hhi, hlo;
        split_bf16(h0v, hhi, hlo);
        uint32_t v  = pack_bf2(hhi, hlo);
        uint32_t pv = __shfl_xor_sync(0xffffffffu, v, 1);
        if (even) {
            uint2 pr;
            pr.x = (v & 0xffffu) | ((pv & 0xffffu) << 16);
            pr.y = (v >> 16) | ((pv >> 16) << 16);
            *(uint2*)(g_hfrag[0] + whoff) = pr;
        }
    }
    __syncthreads();
    if (tid == 0) {
        asm volatile("red.release.gpu.global.add.u32 [%0], %1;"
                     :: "l"(&g_flags[myflag * 64]), "r"(1u) : "memory");
    }

    unsigned* const fp = &g_flags[(unsigned)w * 64];
    float* nc = dout + (size_t)BB * TT * DD;

    for (int t = 0; t < TT; ++t) {
        float xgi = 0.f, xgf = 0.f, xgg = 0.f, xgo = 0.f;
        if (tid < 128) {
            const float* xr = g_xg + ((size_t)pb * TT + t) * EE + pdg;
            xgi = __ldg(xr);
            xgf = __ldg(xr + DD);
            xgg = __ldg(xr + 2 * DD);
            xgo = __ldg(xr + 3 * DD);
        }

        {
            const unsigned tgt = (unsigned)(t + 1) * 16u;
            unsigned v;
            do {
                asm volatile("ld.global.acquire.gpu.u32 %0, [%1];"
                             : "=r"(v) : "l"(fp) : "memory");
            } while (v < tgt);
        }

        float4 acc[4];
#pragma unroll
        for (int n = 0; n < 4; ++n) acc[n] = make_float4(0.f, 0.f, 0.f, 0.f);

        const uint4* ab = (const uint4*)g_hfrag[t & 1];
#pragma unroll
        for (int j = 0; j < 8; ++j) {
            int ks = w * 8 + j;
            uint4 q0 = __ldcg(ab + (ks * 32 + lane) * 2);
            uint4 q1 = __ldcg(ab + (ks * 32 + lane) * 2 + 1);
            uint4 ahi = make_uint4(q0.x, q0.z, q1.x, q1.z);
            uint4 alo = make_uint4(q0.y, q0.w, q1.y, q1.w);
#pragma unroll
            for (int n = 0; n < 4; ++n) {
                uint4 b = *(const uint4*)(sm_w + (size_t)(((n * 64 + ks) * 32 + lane)) * 4);
                mma_bf16(acc[n], ahi, b.x, b.y);
                mma_bf16(acc[n], ahi, b.z, b.w);
                mma_bf16(acc[n], alo, b.x, b.y);
            }
        }

        float* rb = red + (t & 1) * RED_FLOATS;
#pragma unroll
        for (int n = 0; n < 4; ++n) {
            *(float4*)(rb + (size_t)(((w * 4 + n) * 32 + lane)) * 4) = acc[n];
        }
        __syncthreads();

        if (tid < 128) {
            float gi = xgi + bi, gf = xgf + bf_, gg = xgg + bgt, go = xgo + bo;
#pragma unroll
            for (int q = 0; q < 8; ++q) {
                const float* rp = rb + (size_t)(q * 4) * 128;
                gi += rp[lane_c * 4 + reg_c];
                gf += rp[128 + lane_c * 4 + reg_c];
                gg += rp[256 + lane_c * 4 + reg_c];
                go += rp[384 + lane_c * 4 + reg_c];
            }
            float iv = fast_sigmoid(gi);
            float fv = fast_sigmoid(gf);
            float gv = fast_tanh(gg);
            float ov = fast_sigmoid(go);
            c_reg    = fv * c_reg + iv * gv;
            float hv = ov * fast_tanh(c_reg);
            h_last   = hv;

            if (t + 1 < TT) {
                __nv_bfloat16 hhi, hlo;
                split_bf16(hv, hhi, hlo);
                uint32_t v  = pack_bf2(hhi, hlo);
                uint32_t pv = __shfl_xor_sync(0xffffffffu, v, 1);
                if (even) {
                    uint2 pr;
                    pr.x = (v & 0xffffu) | ((pv & 0xffffu) << 16);
                    pr.y = (v >> 16) | ((pv >> 16) << 16);
                    *(uint2*)(g_hfrag[(t + 1) & 1] + whoff) = pr;
                }
                asm volatile("bar.sync 1, 128;" ::: "memory");
                if (tid == 0) {
                    asm volatile("red.release.gpu.global.add.u32 [%0], %1;"
                                 :: "l"(&g_flags[myflag * 64]), "r"(1u)
                                 : "memory");
                }
            }
            dout[((size_t)pb * TT + t) * DD + pdg] = hv;
        }
    }

    if (tid < 128) {
        nc[((size_t)pb * DD + pdg) * 2 + 0] = h_last;
        nc[((size_t)pb * DD + pdg) * 2 + 1] = c_reg;
    }

    __syncthreads();
    if (tid == 0) {
        __threadfence();
        unsigned r = atomicAdd(&g_endcnt, 1u);
        if ((r & 127u) == 127u) {
#pragma unroll
            for (int g = 0; g < 8; ++g) g_flags[g * 64] = 0u;
            __threadfence();
        }
    }
}

// ---------------------------------------------------------------------------
// Launch
// ---------------------------------------------------------------------------
extern "C" void kernel_launch(void* const* d_in, const int* in_sizes, int n_in,
                              void* d_out, int out_size) {
    (void)in_sizes; (void)n_in; (void)out_size;
    const float* x     = (const float*)d_in[0];
    const float* carry = (const float*)d_in[1];
    const float* Wi    = (const float*)d_in[2];
    const float* Wh    = (const float*)d_in[3];
    const float* b     = (const float*)d_in[4];
    float* out = (float*)d_out;

    // Phase 0: split inputs into bf16 hi/lo planes
    {
        __nv_bfloat16 *xhi, *xlo, *wihi, *wilo;
        cudaGetSymbolAddress((void**)&xhi,  g_xhi);
        cudaGetSymbolAddress((void**)&xlo,  g_xlo);
        cudaGetSymbolAddress((void**)&wihi, g_wihi);
        cudaGetSymbolAddress((void**)&wilo, g_wilo);
        size_t nx4 = (size_t)BB * TT * DD / 4;
        size_t nw4 = (size_t)DD * EE / 4;
        split_kernel<<<(unsigned)((nx4 + 255) / 256), 256>>>(x, xhi, xlo, nx4);
        split_kernel<<<(unsigned)((nw4 + 255) / 256), 256>>>(Wi, wihi, wilo, nw4);
    }

    // Phase 1: xg = x @ Wi
    cudaFuncSetAttribute(gemm_xg_mma,
                         cudaFuncAttributeMaxDynamicSharedMemorySize,
                         GEMM_SMEM_BYTES);
    dim3 ggrid(EE / 128, (BB * TT) / 128);
    gemm_xg_mma<<<ggrid, 256, GEMM_SMEM_BYTES>>>();

    // Phase 2: recurrence
    cudaFuncSetAttribute(lstm_rec_kernel,
                         cudaFuncAttributeMaxDynamicSharedMemorySize,
                         REC_SMEM_BYTES);
    lstm_rec_kernel<<<REC_BLOCKS, 256, REC_SMEM_BYTES>>>(carry, Wh, b, out);
}